// round 2
// baseline (speedup 1.0000x reference)
#include <cuda_runtime.h>

typedef unsigned long long ULL;

// ---------------- scratch (static device arrays; no runtime alloc) ----------
__device__ float g_base[2048 * 512];   // xf @ Wep1[:2048]  (4 MB)
__device__ float g_p[2048 * 32];       // prior ensemble outputs p[b,e]

// ---------------- packed f32x2 helpers --------------------------------------
__device__ __forceinline__ ULL pack2(float v) {
    ULL r; unsigned u = __float_as_uint(v);
    asm("mov.b64 %0, {%1, %1};" : "=l"(r) : "r"(u));
    return r;
}
__device__ __forceinline__ float2 unpack2(ULL p) {
    unsigned lo, hi;
    asm("mov.b64 {%0, %1}, %2;" : "=r"(lo), "=r"(hi) : "l"(p));
    return make_float2(__uint_as_float(lo), __uint_as_float(hi));
}
#define FFMA2(acc, a, b) asm("fma.rn.f32x2 %0, %1, %2, %0;" : "+l"(acc) : "l"(a), "l"(b))

// ============================================================================
// Kernel 1: base[2048,512] = concat(x,feature)[2048,2048] @ Wep1[0:2048, 0:512]
// Tiled fp32 GEMM, BM=128 BN=64 BK=16, 256 threads, 8x4 per thread,
// FFMA2 packed over the m-dimension, register-prefetch double buffering.
// ============================================================================
__global__ __launch_bounds__(256) void k_base_gemm(
    const float* __restrict__ x, const float* __restrict__ f,
    const float* __restrict__ W1)
{
    const int AS = 130;                 // BM + 2 (de-conflicts transpose stores)
    __shared__ float As[16 * 130];      // As[k][m]
    __shared__ float Bs[16 * 64];       // Bs[k][n]

    const int tid = threadIdx.x;
    const int m0 = blockIdx.y * 128;
    const int n0 = blockIdx.x * 64;
    const int tx = tid & 15;            // n: tx*4
    const int ty = tid >> 4;            // m: ty*8

    // A-load mapping: two float4 loads along k per thread
    const int m_a0 = tid >> 2;              // 0..63
    const int m_a1 = m_a0 + 64;             // 64..127
    const int kq   = (tid & 3) << 2;        // 0,4,8,12
    // B-load mapping: one float4
    const int kb = tid >> 4;                // 0..15
    const int nq = (tid & 15) << 2;         // 0..60

    ULL acc[4][4];
#pragma unroll
    for (int i = 0; i < 4; i++)
#pragma unroll
        for (int j = 0; j < 4; j++) acc[i][j] = 0ULL;

    // prefetch tile 0
    float4 ra0, ra1, rb;
    {
        const int gk = kq;                      // kt = 0
        const float* src = (gk < 1024) ? x : f;
        const int col = gk & 1023;
        ra0 = *(const float4*)&src[(m0 + m_a0) * 1024 + col];
        ra1 = *(const float4*)&src[(m0 + m_a1) * 1024 + col];
        rb  = *(const float4*)&W1[kb * 512 + n0 + nq];
    }

    for (int kt = 0; kt < 128; ++kt) {
        // store current tile
        As[(kq + 0) * AS + m_a0] = ra0.x;
        As[(kq + 1) * AS + m_a0] = ra0.y;
        As[(kq + 2) * AS + m_a0] = ra0.z;
        As[(kq + 3) * AS + m_a0] = ra0.w;
        As[(kq + 0) * AS + m_a1] = ra1.x;
        As[(kq + 1) * AS + m_a1] = ra1.y;
        As[(kq + 2) * AS + m_a1] = ra1.z;
        As[(kq + 3) * AS + m_a1] = ra1.w;
        *(float4*)&Bs[kb * 64 + nq] = rb;
        __syncthreads();

        // prefetch next tile (LDG latency hidden behind compute)
        if (kt + 1 < 128) {
            const int gk = (kt + 1) * 16 + kq;
            const float* src = (gk < 1024) ? x : f;
            const int col = gk & 1023;
            ra0 = *(const float4*)&src[(m0 + m_a0) * 1024 + col];
            ra1 = *(const float4*)&src[(m0 + m_a1) * 1024 + col];
            rb  = *(const float4*)&W1[((kt + 1) * 16 + kb) * 512 + n0 + nq];
        }

#pragma unroll
        for (int k = 0; k < 16; ++k) {
            ULL a[4];
#pragma unroll
            for (int i = 0; i < 4; i++)
                a[i] = *(const ULL*)&As[k * AS + ty * 8 + 2 * i];
#pragma unroll
            for (int j = 0; j < 4; j++) {
                ULL bb = pack2(Bs[k * 64 + tx * 4 + j]);
#pragma unroll
                for (int i = 0; i < 4; i++) FFMA2(acc[i][j], a[i], bb);
            }
        }
        __syncthreads();
    }

#pragma unroll
    for (int i = 0; i < 4; i++)
#pragma unroll
        for (int j = 0; j < 4; j++) {
            float2 v = unpack2(acc[i][j]);
            const int m = m0 + ty * 8 + 2 * i;
            const int n = n0 + tx * 4 + j;
            g_base[m * 512 + n]       = v.x;
            g_base[(m + 1) * 512 + n] = v.y;
        }
}

// ============================================================================
// Kernel 2: prior ensemble.  8 batch rows per block (amortizes the 655 KB Wp1
// read), x staged in smem as [i][r] so FFMA2 packs over batch pairs.
// ============================================================================
__global__ __launch_bounds__(256) void k_prior(
    const float* __restrict__ x,
    const float* __restrict__ Wp1, const float* __restrict__ bp1,
    const float* __restrict__ Wp2, const float* __restrict__ bp2,
    const float* __restrict__ Wp3, const float* __restrict__ bp3)
{
    __shared__ float xs[8 * 1024];      // xs[i*8 + r]
    __shared__ float sh1[8 * 160];      // sh1[r*160 + e*5 + k]

    const int t = threadIdx.x;
    const int b0 = blockIdx.x * 8;

    for (int idx = t; idx < 8192; idx += 256)
        xs[idx] = x[(b0 + (idx & 7)) * 1024 + (idx >> 3)];
    __syncthreads();

    if (t < 160) {
        const int e = t / 5, k = t - e * 5;
        ULL acc[4] = {0ULL, 0ULL, 0ULL, 0ULL};
        const float* wp = Wp1 + e * 5120 + k;       // Wp1[e][i][k], stride 5 over i
#pragma unroll 4
        for (int i = 0; i < 1024; ++i) {
            ULL ww = pack2(wp[i * 5]);
#pragma unroll
            for (int rp = 0; rp < 4; rp++)
                FFMA2(acc[rp], *(const ULL*)&xs[i * 8 + 2 * rp], ww);
        }
        const float bias = bp1[t];                  // bp1[e*5+k] == bp1[t]
#pragma unroll
        for (int rp = 0; rp < 4; rp++) {
            float2 v = unpack2(acc[rp]);
            sh1[(2 * rp) * 160 + t]     = fmaxf(v.x + bias, 0.f);
            sh1[(2 * rp + 1) * 160 + t] = fmaxf(v.y + bias, 0.f);
        }
    }
    __syncthreads();

    {
        const int r = t >> 5, e = t & 31;
        const float* s1 = &sh1[r * 160 + e * 5];
        const float* w2 = Wp2 + e * 25;
        float p = bp3[e];
#pragma unroll
        for (int g = 0; g < 5; ++g) {
            float s = bp2[e * 5 + g];
#pragma unroll
            for (int k = 0; k < 5; ++k) s += s1[k] * w2[k * 5 + g];
            p += fmaxf(s, 0.f) * Wp3[e * 5 + g];
        }
        g_p[(b0 + r) * 32 + e] = p;
    }
}

// ============================================================================
// Kernel 3: fused epinet tail.  2 batch rows per block, 512 threads.
//  Phase A: h[n][j] = relu(base[b,j] + bep1[j] + sum_q z[b,n,q]*Wep1[2048+q, j])
//  Phase B: out[b,n] = sum_o (h[n]·Wep2[:,o] + bep2[o] + p[b,o]) * z[b,n,o]
// ============================================================================
__global__ __launch_bounds__(512) void k_tail(
    const float* __restrict__ z,
    const float* __restrict__ Wep1, const float* __restrict__ bep1,
    const float* __restrict__ Wep2, const float* __restrict__ bep2,
    float* __restrict__ out)
{
    __shared__ float zs[32 * 16];       // zs[q*16 + bl*8 + n]
    __shared__ float ps[64];            // p for both rows
    __shared__ float hs[16 * 512];      // hs[(bl*8+n)*512 + j]

    const int t = threadIdx.x;
    const int b0 = blockIdx.x * 2;

    {   // load z transposed: zs[q][bl*8+n]
        const int n = t & 7, bl = (t >> 3) & 1, q = t >> 4;
        zs[t] = z[((b0 + bl) * 8 + n) * 32 + q];
    }
    if (t < 64) ps[t] = g_p[b0 * 32 + t];
    __syncthreads();

    // ---- phase A: j = t ----
    {
        const int j = t;
        const float* W1z = Wep1 + 2048 * 512;
        const float be = bep1[j];
        ULL acc[8];
#pragma unroll
        for (int bl = 0; bl < 2; ++bl) {
            ULL pb = pack2(g_base[(b0 + bl) * 512 + j] + be);
#pragma unroll
            for (int np = 0; np < 4; np++) acc[bl * 4 + np] = pb;
        }
#pragma unroll 4
        for (int q = 0; q < 32; ++q) {
            ULL ww = pack2(W1z[q * 512 + j]);
#pragma unroll
            for (int u = 0; u < 8; ++u)
                FFMA2(acc[u], *(const ULL*)&zs[q * 16 + 2 * u], ww);
        }
#pragma unroll
        for (int u = 0; u < 8; ++u) {
            float2 v = unpack2(acc[u]);
            hs[(2 * u) * 512 + j]     = fmaxf(v.x, 0.f);
            hs[(2 * u + 1) * 512 + j] = fmaxf(v.y, 0.f);
        }
    }
    __syncthreads();

    // ---- phase B: warp w = (bl*8+n), lane = o ----
    {
        const int w = t >> 5;           // 0..15
        const int o = t & 31;
        const float* hrow = &hs[w * 512];
        float acc = 0.f;
#pragma unroll 4
        for (int j = 0; j < 512; ++j) acc += hrow[j] * Wep2[j * 32 + o];
        const int bl = w >> 3, n = w & 7;
        float v = (acc + bep2[o] + ps[bl * 32 + o]) * zs[o * 16 + w];
#pragma unroll
        for (int off = 16; off > 0; off >>= 1)
            v += __shfl_xor_sync(0xffffffffu, v, off);
        if (o == 0) out[(b0 + bl) * 8 + n] = v;
    }
}

// ============================================================================
extern "C" void kernel_launch(void* const* d_in, const int* in_sizes, int n_in,
                              void* d_out, int out_size)
{
    const float* x    = (const float*)d_in[0];
    const float* feat = (const float*)d_in[1];
    const float* z    = (const float*)d_in[2];
    const float* Wep1 = (const float*)d_in[3];
    const float* bep1 = (const float*)d_in[4];
    const float* Wep2 = (const float*)d_in[5];
    const float* bep2 = (const float*)d_in[6];
    const float* Wp1  = (const float*)d_in[7];
    const float* bp1  = (const float*)d_in[8];
    const float* Wp2  = (const float*)d_in[9];
    const float* bp2  = (const float*)d_in[10];
    const float* Wp3  = (const float*)d_in[11];
    const float* bp3  = (const float*)d_in[12];
    float* out = (float*)d_out;

    k_base_gemm<<<dim3(8, 16), 256>>>(x, feat, Wep1);
    k_prior<<<256, 256>>>(x, Wp1, bp1, Wp2, bp2, Wp3, bp3);
    k_tail<<<1024, 512>>>(z, Wep1, bep1, Wep2, bep2, out);
}

// round 3
// speedup vs baseline: 1.0079x; 1.0079x over previous
#include <cuda_runtime.h>

typedef unsigned long long ULL;

// ---------------- scratch (static device arrays; no runtime alloc) ----------
__device__ float g_base[2048 * 512];   // xf @ Wep1[:2048]  (4 MB)
__device__ float g_p[2048 * 32];       // prior ensemble outputs p[b,e]

// ---------------- packed f32x2 helpers --------------------------------------
__device__ __forceinline__ ULL pack2(float v) {
    ULL r; unsigned u = __float_as_uint(v);
    asm("mov.b64 %0, {%1, %1};" : "=l"(r) : "r"(u));
    return r;
}
__device__ __forceinline__ float2 unpack2(ULL p) {
    unsigned lo, hi;
    asm("mov.b64 {%0, %1}, %2;" : "=r"(lo), "=r"(hi) : "l"(p));
    return make_float2(__uint_as_float(lo), __uint_as_float(hi));
}
#define FFMA2(acc, a, b) asm("fma.rn.f32x2 %0, %1, %2, %0;" : "+l"(acc) : "l"(a), "l"(b))

// ============================================================================
// Kernel 1: base[2048,512] = concat(x,feature)[2048,2048] @ Wep1[0:2048, 0:512]
// Tiled fp32 GEMM, BM=128 BN=64 BK=16, 256 threads, 8x4 per thread,
// FFMA2 packed over the m-dimension, register-prefetch double buffering.
// ============================================================================
__global__ __launch_bounds__(256) void k_base_gemm(
    const float* __restrict__ x, const float* __restrict__ f,
    const float* __restrict__ W1)
{
    const int AS = 130;                 // BM + 2 (de-conflicts transpose stores)
    __shared__ float As[16 * 130];      // As[k][m]
    __shared__ float Bs[16 * 64];       // Bs[k][n]

    const int tid = threadIdx.x;
    const int m0 = blockIdx.y * 128;
    const int n0 = blockIdx.x * 64;
    const int tx = tid & 15;            // n: tx*4
    const int ty = tid >> 4;            // m: ty*8

    // A-load mapping: two float4 loads along k per thread
    const int m_a0 = tid >> 2;              // 0..63
    const int m_a1 = m_a0 + 64;             // 64..127
    const int kq   = (tid & 3) << 2;        // 0,4,8,12
    // B-load mapping: one float4
    const int kb = tid >> 4;                // 0..15
    const int nq = (tid & 15) << 2;         // 0..60

    ULL acc[4][4];
#pragma unroll
    for (int i = 0; i < 4; i++)
#pragma unroll
        for (int j = 0; j < 4; j++) acc[i][j] = 0ULL;

    // prefetch tile 0
    float4 ra0, ra1, rb;
    {
        const int gk = kq;                      // kt = 0
        const float* src = (gk < 1024) ? x : f;
        const int col = gk & 1023;
        ra0 = *(const float4*)&src[(m0 + m_a0) * 1024 + col];
        ra1 = *(const float4*)&src[(m0 + m_a1) * 1024 + col];
        rb  = *(const float4*)&W1[kb * 512 + n0 + nq];
    }

    for (int kt = 0; kt < 128; ++kt) {
        // store current tile
        As[(kq + 0) * AS + m_a0] = ra0.x;
        As[(kq + 1) * AS + m_a0] = ra0.y;
        As[(kq + 2) * AS + m_a0] = ra0.z;
        As[(kq + 3) * AS + m_a0] = ra0.w;
        As[(kq + 0) * AS + m_a1] = ra1.x;
        As[(kq + 1) * AS + m_a1] = ra1.y;
        As[(kq + 2) * AS + m_a1] = ra1.z;
        As[(kq + 3) * AS + m_a1] = ra1.w;
        *(float4*)&Bs[kb * 64 + nq] = rb;
        __syncthreads();

        // prefetch next tile (LDG latency hidden behind compute)
        if (kt + 1 < 128) {
            const int gk = (kt + 1) * 16 + kq;
            const float* src = (gk < 1024) ? x : f;
            const int col = gk & 1023;
            ra0 = *(const float4*)&src[(m0 + m_a0) * 1024 + col];
            ra1 = *(const float4*)&src[(m0 + m_a1) * 1024 + col];
            rb  = *(const float4*)&W1[((kt + 1) * 16 + kb) * 512 + n0 + nq];
        }

#pragma unroll
        for (int k = 0; k < 16; ++k) {
            ULL a[4];
#pragma unroll
            for (int i = 0; i < 4; i++)
                a[i] = *(const ULL*)&As[k * AS + ty * 8 + 2 * i];
#pragma unroll
            for (int j = 0; j < 4; j++) {
                ULL bb = pack2(Bs[k * 64 + tx * 4 + j]);
#pragma unroll
                for (int i = 0; i < 4; i++) FFMA2(acc[i][j], a[i], bb);
            }
        }
        __syncthreads();
    }

#pragma unroll
    for (int i = 0; i < 4; i++)
#pragma unroll
        for (int j = 0; j < 4; j++) {
            float2 v = unpack2(acc[i][j]);
            const int m = m0 + ty * 8 + 2 * i;
            const int n = n0 + tx * 4 + j;
            g_base[m * 512 + n]       = v.x;
            g_base[(m + 1) * 512 + n] = v.y;
        }
}

// ============================================================================
// Kernel 2: prior ensemble.  8 batch rows per block (amortizes the 655 KB Wp1
// read), x staged in smem as [i][r] so FFMA2 packs over batch pairs.
// ============================================================================
__global__ __launch_bounds__(256) void k_prior(
    const float* __restrict__ x,
    const float* __restrict__ Wp1, const float* __restrict__ bp1,
    const float* __restrict__ Wp2, const float* __restrict__ bp2,
    const float* __restrict__ Wp3, const float* __restrict__ bp3)
{
    __shared__ float xs[8 * 1024];      // xs[i*8 + r]
    __shared__ float sh1[8 * 160];      // sh1[r*160 + e*5 + k]

    const int t = threadIdx.x;
    const int b0 = blockIdx.x * 8;

    for (int idx = t; idx < 8192; idx += 256)
        xs[idx] = x[(b0 + (idx & 7)) * 1024 + (idx >> 3)];
    __syncthreads();

    if (t < 160) {
        const int e = t / 5, k = t - e * 5;
        ULL acc[4] = {0ULL, 0ULL, 0ULL, 0ULL};
        const float* wp = Wp1 + e * 5120 + k;       // Wp1[e][i][k], stride 5 over i
#pragma unroll 4
        for (int i = 0; i < 1024; ++i) {
            ULL ww = pack2(wp[i * 5]);
#pragma unroll
            for (int rp = 0; rp < 4; rp++)
                FFMA2(acc[rp], *(const ULL*)&xs[i * 8 + 2 * rp], ww);
        }
        const float bias = bp1[t];                  // bp1[e*5+k] == bp1[t]
#pragma unroll
        for (int rp = 0; rp < 4; rp++) {
            float2 v = unpack2(acc[rp]);
            sh1[(2 * rp) * 160 + t]     = fmaxf(v.x + bias, 0.f);
            sh1[(2 * rp + 1) * 160 + t] = fmaxf(v.y + bias, 0.f);
        }
    }
    __syncthreads();

    {
        const int r = t >> 5, e = t & 31;
        const float* s1 = &sh1[r * 160 + e * 5];
        const float* w2 = Wp2 + e * 25;
        float p = bp3[e];
#pragma unroll
        for (int g = 0; g < 5; ++g) {
            float s = bp2[e * 5 + g];
#pragma unroll
            for (int k = 0; k < 5; ++k) s += s1[k] * w2[k * 5 + g];
            p += fmaxf(s, 0.f) * Wp3[e * 5 + g];
        }
        g_p[(b0 + r) * 32 + e] = p;
    }
}

// ============================================================================
// Kernel 3: fused epinet tail.  2 batch rows per block, 512 threads.
//  Phase A: h[n][j] = relu(base[b,j] + bep1[j] + sum_q z[b,n,q]*Wep1[2048+q, j])
//  Phase B: out[b,n] = sum_o (h[n]·Wep2[:,o] + bep2[o] + p[b,o]) * z[b,n,o]
// ============================================================================
__global__ __launch_bounds__(512) void k_tail(
    const float* __restrict__ z,
    const float* __restrict__ Wep1, const float* __restrict__ bep1,
    const float* __restrict__ Wep2, const float* __restrict__ bep2,
    float* __restrict__ out)
{
    __shared__ float zs[32 * 16];       // zs[q*16 + bl*8 + n]
    __shared__ float ps[64];            // p for both rows
    __shared__ float hs[16 * 512];      // hs[(bl*8+n)*512 + j]

    const int t = threadIdx.x;
    const int b0 = blockIdx.x * 2;

    {   // load z transposed: zs[q][bl*8+n]
        const int n = t & 7, bl = (t >> 3) & 1, q = t >> 4;
        zs[t] = z[((b0 + bl) * 8 + n) * 32 + q];
    }
    if (t < 64) ps[t] = g_p[b0 * 32 + t];
    __syncthreads();

    // ---- phase A: j = t ----
    {
        const int j = t;
        const float* W1z = Wep1 + 2048 * 512;
        const float be = bep1[j];
        ULL acc[8];
#pragma unroll
        for (int bl = 0; bl < 2; ++bl) {
            ULL pb = pack2(g_base[(b0 + bl) * 512 + j] + be);
#pragma unroll
            for (int np = 0; np < 4; np++) acc[bl * 4 + np] = pb;
        }
#pragma unroll 4
        for (int q = 0; q < 32; ++q) {
            ULL ww = pack2(W1z[q * 512 + j]);
#pragma unroll
            for (int u = 0; u < 8; ++u)
                FFMA2(acc[u], *(const ULL*)&zs[q * 16 + 2 * u], ww);
        }
#pragma unroll
        for (int u = 0; u < 8; ++u) {
            float2 v = unpack2(acc[u]);
            hs[(2 * u) * 512 + j]     = fmaxf(v.x, 0.f);
            hs[(2 * u + 1) * 512 + j] = fmaxf(v.y, 0.f);
        }
    }
    __syncthreads();

    // ---- phase B: warp w = (bl*8+n), lane = o ----
    {
        const int w = t >> 5;           // 0..15
        const int o = t & 31;
        const float* hrow = &hs[w * 512];
        float acc = 0.f;
#pragma unroll 4
        for (int j = 0; j < 512; ++j) acc += hrow[j] * Wep2[j * 32 + o];
        const int bl = w >> 3, n = w & 7;
        float v = (acc + bep2[o] + ps[bl * 32 + o]) * zs[o * 16 + w];
#pragma unroll
        for (int off = 16; off > 0; off >>= 1)
            v += __shfl_xor_sync(0xffffffffu, v, off);
        if (o == 0) out[(b0 + bl) * 8 + n] = v;
    }
}

// ============================================================================
extern "C" void kernel_launch(void* const* d_in, const int* in_sizes, int n_in,
                              void* d_out, int out_size)
{
    const float* x    = (const float*)d_in[0];
    const float* feat = (const float*)d_in[1];
    const float* z    = (const float*)d_in[2];
    const float* Wep1 = (const float*)d_in[3];
    const float* bep1 = (const float*)d_in[4];
    const float* Wep2 = (const float*)d_in[5];
    const float* bep2 = (const float*)d_in[6];
    const float* Wp1  = (const float*)d_in[7];
    const float* bp1  = (const float*)d_in[8];
    const float* Wp2  = (const float*)d_in[9];
    const float* bp2  = (const float*)d_in[10];
    const float* Wp3  = (const float*)d_in[11];
    const float* bp3  = (const float*)d_in[12];
    float* out = (float*)d_out;

    k_base_gemm<<<dim3(8, 16), 256>>>(x, feat, Wep1);
    k_prior<<<256, 256>>>(x, Wp1, bp1, Wp2, bp2, Wp3, bp3);
    k_tail<<<1024, 512>>>(z, Wep1, bep1, Wep2, bep2, out);
}

// round 5
// speedup vs baseline: 1.5081x; 1.4963x over previous
#include <cuda_runtime.h>
#include <cuda_bf16.h>
#include <cstdint>

typedef unsigned long long ULL;

// ---------------- scratch (static device arrays; no runtime alloc) ----------
__device__ __nv_bfloat16 g_A2[2048L * 6144];   // [Ah | Al | Ah]      24 MB
__device__ __nv_bfloat16 g_W2[6144L * 704];    // [Wh ; Wh ; Wl] k-major  8.25 MB
#define PART_SZ (2048L * 704)
__device__ float g_part[4 * PART_SZ];          // K-split partial outputs 23 MB
__device__ float g_p[2048 * 32];               // prior ensemble outputs
__device__ float g_wz[16384L * 512];           // wz[bn][j] = Wep2[j,:].z[bn,:]

// ---------------- packed f32x2 helpers --------------------------------------
__device__ __forceinline__ ULL pack2(float v) {
    ULL r; unsigned u = __float_as_uint(v);
    asm("mov.b64 %0, {%1, %1};" : "=l"(r) : "r"(u));
    return r;
}
__device__ __forceinline__ float2 unpack2(ULL p) {
    unsigned lo, hi;
    asm("mov.b64 {%0, %1}, %2;" : "=r"(lo), "=r"(hi) : "l"(p));
    return make_float2(__uint_as_float(lo), __uint_as_float(hi));
}
#define FFMA2(acc, a, b) asm("fma.rn.f32x2 %0, %1, %2, %0;" : "+l"(acc) : "l"(a), "l"(b))

// ---------------- mma.sync / ldmatrix / cp.async (sm_80 baseline) -----------
__device__ __forceinline__ uint32_t smem_u32(const void* p) {
    uint32_t a;
    asm("{ .reg .u64 t; cvta.to.shared.u64 t, %1; cvt.u32.u64 %0, t; }" : "=r"(a) : "l"(p));
    return a;
}
#define SW128(o) ((o) ^ (((o) >> 3) & 0x70))

#define LDSM_X4(r0, r1, r2, r3, addr) \
    asm volatile("ldmatrix.sync.aligned.m8n8.x4.shared.b16 {%0,%1,%2,%3}, [%4];" \
                 : "=r"(r0), "=r"(r1), "=r"(r2), "=r"(r3) : "r"(addr))
#define LDSM_X4T(r0, r1, r2, r3, addr) \
    asm volatile("ldmatrix.sync.aligned.m8n8.x4.trans.shared.b16 {%0,%1,%2,%3}, [%4];" \
                 : "=r"(r0), "=r"(r1), "=r"(r2), "=r"(r3) : "r"(addr))
#define MMA16816(d, a, b) \
    asm volatile("mma.sync.aligned.m16n8k16.row.col.f32.bf16.bf16.f32 " \
                 "{%0,%1,%2,%3}, {%4,%5,%6,%7}, {%8,%9}, {%0,%1,%2,%3};" \
                 : "+f"((d)[0]), "+f"((d)[1]), "+f"((d)[2]), "+f"((d)[3]) \
                 : "r"((a)[0]), "r"((a)[1]), "r"((a)[2]), "r"((a)[3]), \
                   "r"((b)[0]), "r"((b)[1]))
#define CP16(dst, src) \
    asm volatile("cp.async.cg.shared.global [%0], [%1], 16;" :: "r"(dst), "l"(src))
#define CP_COMMIT() asm volatile("cp.async.commit_group;" ::: "memory")
#define CP_WAIT2()  asm volatile("cp.async.wait_group 2;" ::: "memory")

// ============================================================================
// Convert A': [2048 m][6144 k] = [Ah | Al | Ah], source = concat(x, feature).
// ============================================================================
__global__ __launch_bounds__(256) void k_convert_A2(const float* __restrict__ x,
                                                    const float* __restrict__ f) {
    int idx = blockIdx.x * 256 + threadIdx.x;        // over 2048*768 vec8
    int m = idx / 768;
    int v = idx - m * 768;
    int k = v * 8;
    int seg = k >> 11;
    int kk = k & 2047;
    const float* src = (kk < 1024) ? (x + (size_t)m * 1024 + kk)
                                   : (f + (size_t)m * 1024 + (kk - 1024));
    float4 f0 = *(const float4*)src;
    float4 f1 = *(const float4*)(src + 4);
    float vv[8] = {f0.x, f0.y, f0.z, f0.w, f1.x, f1.y, f1.z, f1.w};
    union { __nv_bfloat16 h[8]; uint4 u; } O;
#pragma unroll
    for (int e = 0; e < 8; ++e) {
        __nv_bfloat16 hb = __float2bfloat16(vv[e]);
        O.h[e] = (seg == 1) ? __float2bfloat16(vv[e] - __bfloat162float(hb)) : hb;
    }
    *(uint4*)(g_A2 + (size_t)m * 6144 + k) = O.u;
}

// ============================================================================
// Convert W': [6144 k][704 n] = [Wh ; Wh ; Wl], cols 0-511 = Wep1 (k-major as
// stored!), cols 512-671 = Wp1 fold (zero for k>=1024), cols 672-703 = zero.
// ============================================================================
__global__ __launch_bounds__(256) void k_convert_W2(const float* __restrict__ Wep1,
                                                    const float* __restrict__ Wp1) {
    int idx = blockIdx.x * 256 + threadIdx.x;        // over 6144*88 vec8
    int k = idx / 88;
    int v = idx - k * 88;
    int n = v * 8;
    int seg = k >> 11;
    int kk = k & 2047;
    float vv[8];
    if (n < 512) {
        float4 f0 = *(const float4*)&Wep1[(size_t)kk * 512 + n];
        float4 f1 = *(const float4*)&Wep1[(size_t)kk * 512 + n + 4];
        vv[0] = f0.x; vv[1] = f0.y; vv[2] = f0.z; vv[3] = f0.w;
        vv[4] = f1.x; vv[5] = f1.y; vv[6] = f1.z; vv[7] = f1.w;
    } else if (n < 672 && kk < 1024) {
#pragma unroll
        for (int e = 0; e < 8; ++e) {
            int u = n + e - 512, en = u / 5, r = u - en * 5;
            vv[e] = Wp1[en * 5120 + kk * 5 + r];
        }
    } else {
#pragma unroll
        for (int e = 0; e < 8; ++e) vv[e] = 0.f;
    }
    union { __nv_bfloat16 h[8]; uint4 u; } O;
#pragma unroll
    for (int e = 0; e < 8; ++e) {
        __nv_bfloat16 hb = __float2bfloat16(vv[e]);
        O.h[e] = (seg == 2) ? __float2bfloat16(vv[e] - __bfloat162float(hb)) : hb;
    }
    *(uint4*)(g_W2 + (size_t)k * 704 + n) = O.u;
}

// ============================================================================
// HMMA GEMM: D[2048,704] (+=) A'[2048,6144] @ W'[6144,704], K-split 4.
// BM=128 BN=64 BK=64, 256 thr (8 warps, 4x2 grid of 32x32 warp tiles),
// 4-stage cp.async pipeline, SW128 smem, ldmatrix(.trans for B) + mma.sync.
// ============================================================================
__device__ __forceinline__ void gemm_issue(int tid, int m0, int n0, int kchunk,
                                           uint32_t sb, int stage) {
    const __nv_bfloat16* Ab = g_A2 + (size_t)m0 * 6144 + (size_t)kchunk * 64;
    const __nv_bfloat16* Bb = g_W2 + (size_t)kchunk * 64 * 704 + n0;
    uint32_t sA = sb + stage * 24576;
    uint32_t sB = sA + 16384;
#pragma unroll
    for (int i = 0; i < 4; ++i) {
        int v = tid * 4 + i, m = v >> 3, q = v & 7;
        uint32_t d = sA + SW128((uint32_t)(m * 128 + q * 16));
        CP16(d, Ab + (size_t)m * 6144 + q * 8);
    }
#pragma unroll
    for (int i = 0; i < 2; ++i) {
        int v = tid * 2 + i, kr = v >> 3, q = v & 7;
        uint32_t d = sB + SW128((uint32_t)(kr * 128 + q * 16));
        CP16(d, Bb + (size_t)kr * 704 + q * 8);
    }
}

__global__ __launch_bounds__(256, 2) void k_gemm() {
    extern __shared__ __align__(1024) char smem[];
    const uint32_t sb = smem_u32(smem);
    const int tid = threadIdx.x, lane = tid & 31, wid = tid >> 5;
    const int m0 = blockIdx.y * 128;
    const int n0 = blockIdx.x * 64;
    const int kc0 = blockIdx.z * 24;
    const int warp_m = (wid & 3) * 32;
    const int warp_n = (wid >> 2) * 32;

    float acc[2][4][4] = {};

    gemm_issue(tid, m0, n0, kc0 + 0, sb, 0); CP_COMMIT();
    gemm_issue(tid, m0, n0, kc0 + 1, sb, 1); CP_COMMIT();
    gemm_issue(tid, m0, n0, kc0 + 2, sb, 2); CP_COMMIT();

    for (int c = 0; c < 24; ++c) {
        CP_WAIT2();
        __syncthreads();
        if (c + 3 < 24) gemm_issue(tid, m0, n0, kc0 + c + 3, sb, (c + 3) & 3);
        CP_COMMIT();

        const uint32_t sA = sb + (c & 3) * 24576;
        const uint32_t sB = sA + 16384;
#pragma unroll
        for (int s = 0; s < 4; ++s) {
            uint32_t aF[2][4], bF[4][2];
#pragma unroll
            for (int i = 0; i < 2; ++i) {
                int row = warp_m + i * 16 + ((lane >> 3) & 1) * 8 + (lane & 7);
                int kh  = s * 16 + (lane >> 4) * 8;
                uint32_t ad = sA + SW128((uint32_t)(row * 128 + kh * 2));
                LDSM_X4(aF[i][0], aF[i][1], aF[i][2], aF[i][3], ad);
            }
#pragma unroll
            for (int j2 = 0; j2 < 2; ++j2) {
                int kr = s * 16 + ((lane >> 3) & 1) * 8 + (lane & 7);
                int nc = warp_n + j2 * 16 + (lane >> 4) * 8;
                uint32_t bd = sB + SW128((uint32_t)(kr * 128 + nc * 2));
                LDSM_X4T(bF[j2 * 2][0], bF[j2 * 2][1],
                         bF[j2 * 2 + 1][0], bF[j2 * 2 + 1][1], bd);
            }
#pragma unroll
            for (int i = 0; i < 2; ++i)
#pragma unroll
                for (int j = 0; j < 4; ++j)
                    MMA16816(acc[i][j], aF[i], bF[j]);
        }
    }

    float* dst = g_part + (size_t)blockIdx.z * PART_SZ;
#pragma unroll
    for (int i = 0; i < 2; ++i)
#pragma unroll
        for (int j = 0; j < 4; ++j) {
            int r = m0 + warp_m + i * 16 + (lane >> 2);
            int cC = n0 + warp_n + j * 8 + (lane & 3) * 2;
            *(float2*)&dst[(size_t)r * 704 + cC] = make_float2(acc[i][j][0], acc[i][j][1]);
            *(float2*)&dst[(size_t)(r + 8) * 704 + cC] = make_float2(acc[i][j][2], acc[i][j][3]);
        }
}

// ============================================================================
// Prior tail: layers 2-3 of the ensemble; h1 pre-bias = sum of the 4 partials
// at g_part cols 512+.
// ============================================================================
__global__ __launch_bounds__(256) void k_prior_tail(
    const float* __restrict__ bp1, const float* __restrict__ Wp2,
    const float* __restrict__ bp2, const float* __restrict__ Wp3,
    const float* __restrict__ bp3)
{
    const int t = threadIdx.x;
    const int b = blockIdx.x * 8 + (t >> 5);
    const int e = t & 31;
    const size_t off = (size_t)b * 704 + 512 + e * 5;
    float s1[5];
#pragma unroll
    for (int k = 0; k < 5; ++k) {
        float a = bp1[e * 5 + k];
#pragma unroll
        for (int s = 0; s < 4; ++s) a += g_part[s * PART_SZ + off + k];
        s1[k] = fmaxf(a, 0.f);
    }
    float p = bp3[e];
#pragma unroll
    for (int g = 0; g < 5; ++g) {
        float s = bp2[e * 5 + g];
#pragma unroll
        for (int k = 0; k < 5; ++k) s += s1[k] * Wp2[e * 25 + k * 5 + g];
        p += fmaxf(s, 0.f) * Wp3[e * 5 + g];
    }
    g_p[b * 32 + e] = p;
}

// ============================================================================
// wz[bn][j] = sum_o Wep2[j][o] * z[bn][o].  16 rows/block, Wep2 register-resident.
// ============================================================================
__global__ __launch_bounds__(256) void k_wz(const float* __restrict__ z,
                                            const float* __restrict__ W2)
{
    __shared__ float zs[16 * 32];
    const int t = threadIdx.x;
    const int r0 = blockIdx.x * 16;
    for (int i = t; i < 512; i += 256) zs[i] = z[(size_t)r0 * 32 + i];
    __syncthreads();

    const int j0 = t, j1 = t + 256;
    float4 w0[8], w1[8];
#pragma unroll
    for (int q = 0; q < 8; ++q) {
        w0[q] = *(const float4*)&W2[j0 * 32 + q * 4];
        w1[q] = *(const float4*)&W2[j1 * 32 + q * 4];
    }
#pragma unroll 4
    for (int r = 0; r < 16; ++r) {
        float a0 = 0.f, a1 = 0.f;
#pragma unroll
        for (int q = 0; q < 8; ++q) {
            float4 zv = *(const float4*)&zs[r * 32 + q * 4];
            a0 += zv.x * w0[q].x + zv.y * w0[q].y + zv.z * w0[q].z + zv.w * w0[q].w;
            a1 += zv.x * w1[q].x + zv.y * w1[q].y + zv.z * w1[q].z + zv.w * w1[q].w;
        }
        g_wz[(size_t)(r0 + r) * 512 + j0] = a0;
        g_wz[(size_t)(r0 + r) * 512 + j1] = a1;
    }
}

// ============================================================================
// Fused epinet tail: 2 b-rows (16 (b,n) rows) per block, 512 threads.
//  A: h[row][j] = relu(base[b,j]+bep1[j] + sum_q z[row][q]*Wep1[2048+q, j])
//  B: out[row]  = h[row].wz[row] + sum_o (bep2[o]+p[b,o])*z[row][o]
// ============================================================================
__global__ __launch_bounds__(512) void k_tail(
    const float* __restrict__ z, const float* __restrict__ Wep1,
    const float* __restrict__ bep1, const float* __restrict__ bep2,
    float* __restrict__ out)
{
    __shared__ float zsT[32 * 16];      // zsT[q][row]
    __shared__ float zs[16 * 32];       // zs[row][o]
    __shared__ float ps[64];
    __shared__ float hs[16 * 512];      // hs[row][j]

    const int t = threadIdx.x;
    const int r0 = blockIdx.x * 16;     // flat (b,n) row base
    const int b0 = blockIdx.x * 2;

    {
        const int row = t >> 5, o = t & 31;
        float v = z[(size_t)(r0 + row) * 32 + o];
        zs[row * 32 + o] = v;
        zsT[o * 16 + row] = v;
    }
    if (t < 64) ps[t] = g_p[b0 * 32 + t];
    __syncthreads();

    // ---- phase A: j = t ----
    {
        const int j = t;
        const float* W1z = Wep1 + 2048 * 512;
        const float be = bep1[j];
        float base0 = be, base1 = be;
#pragma unroll
        for (int s = 0; s < 4; ++s) {
            base0 += g_part[s * PART_SZ + (size_t)b0 * 704 + j];
            base1 += g_part[s * PART_SZ + (size_t)(b0 + 1) * 704 + j];
        }
        ULL acc[8];
#pragma unroll
        for (int u = 0; u < 8; ++u) acc[u] = pack2(u < 4 ? base0 : base1);
#pragma unroll 4
        for (int q = 0; q < 32; ++q) {
            ULL ww = pack2(W1z[q * 512 + j]);
#pragma unroll
            for (int u = 0; u < 8; ++u)
                FFMA2(acc[u], *(const ULL*)&zsT[q * 16 + 2 * u], ww);
        }
#pragma unroll
        for (int u = 0; u < 8; ++u) {
            float2 v = unpack2(acc[u]);
            hs[(2 * u) * 512 + j]     = fmaxf(v.x, 0.f);
            hs[(2 * u + 1) * 512 + j] = fmaxf(v.y, 0.f);
        }
    }
    __syncthreads();

    // ---- phase B: warp w = row, lane l ----
    {
        const int w = t >> 5, l = t & 31;
        const float4* h4 = (const float4*)&hs[w * 512];
        const float4* w4 = (const float4*)&g_wz[(size_t)(r0 + w) * 512];
        float acc = 0.f;
#pragma unroll
        for (int it = 0; it < 4; ++it) {
            float4 hv = h4[it * 32 + l];
            float4 wv = w4[it * 32 + l];
            acc += hv.x * wv.x + hv.y * wv.y + hv.z * wv.z + hv.w * wv.w;
        }
        acc += (bep2[l] + ps[(w >> 3) * 32 + l]) * zs[w * 32 + l];
#pragma unroll
        for (int off = 16; off > 0; off >>= 1)
            acc += __shfl_xor_sync(0xffffffffu, acc, off);
        if (l == 0) out[r0 + w] = acc;
    }
}

// ============================================================================
extern "C" void kernel_launch(void* const* d_in, const int* in_sizes, int n_in,
                              void* d_out, int out_size)
{
    const float* x    = (const float*)d_in[0];
    const float* feat = (const float*)d_in[1];
    const float* z    = (const float*)d_in[2];
    const float* Wep1 = (const float*)d_in[3];
    const float* bep1 = (const float*)d_in[4];
    const float* Wep2 = (const float*)d_in[5];
    const float* bep2 = (const float*)d_in[6];
    const float* Wp1  = (const float*)d_in[7];
    const float* bp1  = (const float*)d_in[8];
    const float* Wp2  = (const float*)d_in[9];
    const float* bp2  = (const float*)d_in[10];
    const float* Wp3  = (const float*)d_in[11];
    const float* bp3  = (const float*)d_in[12];
    float* out = (float*)d_out;

    static int smem_set = 0;
    if (!smem_set) {
        cudaFuncSetAttribute(k_gemm, cudaFuncAttributeMaxDynamicSharedMemorySize, 98304);
        smem_set = 1;
    }

    k_convert_A2<<<6144, 256>>>(x, feat);
    k_convert_W2<<<2112, 256>>>(Wep1, Wp1);
    k_wz<<<1024, 256>>>(z, Wep2);
    k_gemm<<<dim3(11, 16, 4), 256, 98304>>>();
    k_prior_tail<<<256, 256>>>(bp1, Wp2, bp2, Wp3, bp3);
    k_tail<<<1024, 512>>>(z, Wep1, bep1, bep2, out);
}